// round 9
// baseline (speedup 1.0000x reference)
#include <cuda_runtime.h>
#include <cuda_fp16.h>
#include <cstdint>

// ---------------------------------------------------------------------------
// Problem dims (fixed)
// ---------------------------------------------------------------------------
#define M_DIM 8192
#define K_DIM 4096
#define N_DIM 11008
#define NPACK 1376   // N/8

// GEMM tiling: CTA 128x128, warp tile 64x32 (2Mx4N), BK=32, 6 stages, 2 CTA/SM
// Smem layout: XOR-swizzled, 64B rows: phys(r,c16) = r*64 + ((c16 ^ ((r>>1)&3))<<4)
#define BM 128
#define BN 128
#define BK 32
#define STAGES 6
#define A_STAGE_B (BM * 64)               // 8192 B
#define B_STAGE_B (BN * 64)               // 8192 B
#define STAGE_B   (A_STAGE_B + B_STAGE_B) // 16384 B
#define SMEM_DYN  (STAGES * STAGE_B)      // 98304 B -> 2 CTAs/SM (192 KB)

// Prep-kernel grid split
#define CVT_BLOCKS  16384                 // M*K/(256*8)
#define DQ_BX 43
#define DQ_BY 256
#define DQ_BLOCKS (DQ_BX * DQ_BY)         // 11008

// Scratch (device globals; no runtime allocation)
__device__ __half A_h[(size_t)M_DIM * K_DIM];   // 67 MB
__device__ __half W_h[(size_t)N_DIM * K_DIM];   // 90 MB, [N][K] (col-major B)

// ---------------------------------------------------------------------------
// PTX helpers (base sm_103 ISA only)
// ---------------------------------------------------------------------------
__device__ __forceinline__ uint32_t smem_u32(const void* p) {
    uint32_t a;
    asm("{ .reg .u64 t; cvta.to.shared.u64 t, %1; cvt.u32.u64 %0, t; }"
        : "=r"(a) : "l"(p));
    return a;
}
__device__ __forceinline__ void cp_async16(uint32_t dst, const void* src) {
    asm volatile("cp.async.cg.shared.global [%0], [%1], 16;"
                 :: "r"(dst), "l"(src) : "memory");
}
__device__ __forceinline__ void cp_commit() {
    asm volatile("cp.async.commit_group;" ::: "memory");
}
template <int N>
__device__ __forceinline__ void cp_wait() {
    asm volatile("cp.async.wait_group %0;" :: "n"(N) : "memory");
}
__device__ __forceinline__ void ldmx4(uint32_t* r, uint32_t addr) {
    asm volatile("ldmatrix.sync.aligned.m8n8.x4.shared.b16 {%0,%1,%2,%3}, [%4];"
                 : "=r"(r[0]), "=r"(r[1]), "=r"(r[2]), "=r"(r[3]) : "r"(addr));
}
__device__ __forceinline__ void mma_f16(float* d, const uint32_t* a, const uint32_t* b) {
    asm volatile(
        "mma.sync.aligned.m16n8k16.row.col.f32.f16.f16.f32 "
        "{%0,%1,%2,%3}, {%4,%5,%6,%7}, {%8,%9}, {%0,%1,%2,%3};"
        : "+f"(d[0]), "+f"(d[1]), "+f"(d[2]), "+f"(d[3])
        : "r"(a[0]), "r"(a[1]), "r"(a[2]), "r"(a[3]), "r"(b[0]), "r"(b[1]));
}

// ---------------------------------------------------------------------------
// Prep kernel: blocks [0, CVT_BLOCKS) convert x -> fp16;
//              blocks [CVT_BLOCKS, +DQ_BLOCKS) GPTQ-dequant -> W_h[n][k]
// ---------------------------------------------------------------------------
__global__ void prep_kernel(const float* __restrict__ x,
                            const int* __restrict__ qweight,
                            const int* __restrict__ qzeros,
                            const float* __restrict__ scales) {
    if (blockIdx.x < CVT_BLOCKS) {
        size_t i = ((size_t)blockIdx.x * 256 + threadIdx.x) * 8;
        float4 v0 = *(const float4*)(x + i);
        float4 v1 = *(const float4*)(x + i + 4);
        __half2 h[4];
        h[0] = __floats2half2_rn(v0.x, v0.y);
        h[1] = __floats2half2_rn(v0.z, v0.w);
        h[2] = __floats2half2_rn(v1.x, v1.y);
        h[3] = __floats2half2_rn(v1.z, v1.w);
        *(uint4*)(A_h + i) = *(uint4*)h;
    } else {
        int b   = blockIdx.x - CVT_BLOCKS;
        int n   = (b % DQ_BX) * 256 + threadIdx.x;
        int kp0 = (b / DQ_BX) * 2;
        int g   = kp0 >> 4;

        unsigned zpack = (unsigned)qzeros[g * NPACK + (n >> 3)];
        int zq = (int)((zpack >> ((n & 7) * 4)) & 0xFu) + 1;
        float s = scales[g * N_DIM + n];

        __half2 out[8];
#pragma unroll
        for (int p = 0; p < 2; ++p) {
            unsigned packed = (unsigned)qweight[(kp0 + p) * N_DIM + n];
#pragma unroll
            for (int j = 0; j < 4; ++j) {
                int q0 = (int)((packed >> (8 * j)) & 0xFu);
                int q1 = (int)((packed >> (8 * j + 4)) & 0xFu);
                out[p * 4 + j] = __floats2half2_rn(s * (float)(q0 - zq),
                                                   s * (float)(q1 - zq));
            }
        }
        __half* dst = W_h + (size_t)n * K_DIM + (size_t)kp0 * 8;
        *(uint4*)(dst)     = *(uint4*)(out);
        *(uint4*)(dst + 8) = *(uint4*)(out + 4);
    }
}

// ---------------------------------------------------------------------------
// GEMM: C = A_h * W_h^T via mma.sync m16n8k16 fp16->fp32
// CTA 128x128, 8 warps (2Mx4N, warp 64x32), BK=32, 6-stage cp.async pipeline,
// 2 CTAs/SM. XOR-swizzled smem: conflict-free for BOTH cp.async writes and
// LDSM reads (the 80B-pitch layout had 2-way write conflicts).
// ---------------------------------------------------------------------------
__global__ void __launch_bounds__(256, 2)
gemm_hmma_kernel(float* __restrict__ C) {
    extern __shared__ char dynsmem[];
    const uint32_t sbase = smem_u32(dynsmem);

    const int tid  = threadIdx.x;
    const int wid  = tid >> 5;
    const int lane = tid & 31;
    const int m0 = blockIdx.x * BM;
    const int n0 = blockIdx.y * BN;
    const int wm = (wid & 1) * 64;   // warp M offset
    const int wn = (wid >> 1) * 32;  // warp N offset

    // ---- cp.async mapping: thread -> row tid>>1, 32B half (2 x 16B chunks) ----
    const int wr  = tid >> 1;                         // 0..127
    const int wc0 = (tid & 1) * 2;                    // 16B chunk 0 or 2
    const int wsw = (wr >> 1) & 3;                    // swizzle bits
    const uint32_t wphys0 = (uint32_t)wr * 64 + (uint32_t)((wc0 ^ wsw) << 4);
    const uint32_t wphys1 = (uint32_t)wr * 64 + (uint32_t)(((wc0 + 1) ^ wsw) << 4);
    const __half* gA = A_h + (size_t)(m0 + wr) * K_DIM + wc0 * 8;
    const __half* gB = W_h + (size_t)(n0 + wr) * K_DIM + wc0 * 8;

    // ---- ldmatrix lane offsets (swizzled; ks=1 is ^0x20) ----
    const int arow = wm + (lane & 15);
    const int ac   = lane >> 4;                       // chunk 0/1
    const uint32_t a_off = (uint32_t)arow * 64
                         + (uint32_t)((ac ^ ((arow >> 1) & 3)) << 4);
    const int brow = wn + ((lane >> 4) & 1) * 8 + (lane & 7);
    const int bc   = (lane >> 3) & 1;
    const uint32_t b_off = A_STAGE_B + (uint32_t)brow * 64
                         + (uint32_t)((bc ^ ((brow >> 1) & 3)) << 4);

    float acc[4][4][4];
#pragma unroll
    for (int i = 0; i < 4; ++i)
#pragma unroll
        for (int t = 0; t < 4; ++t)
#pragma unroll
            for (int r = 0; r < 4; ++r) acc[i][t][r] = 0.f;

    const int NIT = K_DIM / BK;   // 128

    // ---- prologue: fill stages 0..4 ----
#pragma unroll
    for (int s = 0; s < STAGES - 1; ++s) {
        uint32_t so = (uint32_t)s * STAGE_B;
        const __half* a = gA + s * BK;
        const __half* b = gB + s * BK;
        cp_async16(sbase + so + wphys0, a);
        cp_async16(sbase + so + wphys1, a + 8);
        cp_async16(sbase + so + A_STAGE_B + wphys0, b);
        cp_async16(sbase + so + A_STAGE_B + wphys1, b + 8);
        cp_commit();
    }

    int st = 0;
    for (int it = 0; it < NIT; ++it) {
        cp_wait<STAGES - 2>();
        __syncthreads();

        int kt = it + STAGES - 1;
        if (kt < NIT) {
            int s2 = kt % STAGES;
            uint32_t so = (uint32_t)s2 * STAGE_B;
            const __half* a = gA + kt * BK;
            const __half* b = gB + kt * BK;
            cp_async16(sbase + so + wphys0, a);
            cp_async16(sbase + so + wphys1, a + 8);
            cp_async16(sbase + so + A_STAGE_B + wphys0, b);
            cp_async16(sbase + so + A_STAGE_B + wphys1, b + 8);
        }
        cp_commit();

        const uint32_t stage = sbase + (uint32_t)st * STAGE_B;
#pragma unroll
        for (int ks = 0; ks < 2; ++ks) {
            const uint32_t kx = ks ? 0x20u : 0u;      // k16 substep: flip chunk bit1
            uint32_t afr[4][4], bfr[4][2];
#pragma unroll
            for (int i = 0; i < 4; ++i)
                ldmx4(afr[i], (stage + a_off + (uint32_t)i * 1024) ^ kx);
#pragma unroll
            for (int j = 0; j < 2; ++j) {
                uint32_t r[4];
                ldmx4(r, (stage + b_off + (uint32_t)j * 1024) ^ kx);
                bfr[2 * j][0] = r[0]; bfr[2 * j][1] = r[1];
                bfr[2 * j + 1][0] = r[2]; bfr[2 * j + 1][1] = r[3];
            }
#pragma unroll
            for (int i = 0; i < 4; ++i)
#pragma unroll
                for (int t = 0; t < 4; ++t)
                    mma_f16(acc[i][t], afr[i], bfr[t]);
        }
        if (++st == STAGES) st = 0;
    }

    // ---- epilogue: direct fp32 stores ----
    const int er = lane >> 2;
    const int ec = (lane & 3) * 2;
#pragma unroll
    for (int i = 0; i < 4; ++i) {
        size_t row0 = (size_t)(m0 + wm + i * 16 + er) * N_DIM;
        size_t row1 = row0 + 8 * N_DIM;
#pragma unroll
        for (int t = 0; t < 4; ++t) {
            int col = n0 + wn + t * 8 + ec;
            *(float2*)(C + row0 + col) = make_float2(acc[i][t][0], acc[i][t][1]);
            *(float2*)(C + row1 + col) = make_float2(acc[i][t][2], acc[i][t][3]);
        }
    }
}

// ---------------------------------------------------------------------------
// Launch
// ---------------------------------------------------------------------------
extern "C" void kernel_launch(void* const* d_in, const int* in_sizes, int n_in,
                              void* d_out, int out_size) {
    const float* x       = (const float*)d_in[0];
    const int*   qweight = (const int*)d_in[1];
    const int*   qzeros  = (const int*)d_in[2];
    const float* scales  = (const float*)d_in[3];
    float* out = (float*)d_out;

    cudaFuncSetAttribute(gemm_hmma_kernel,
                         cudaFuncAttributeMaxDynamicSharedMemorySize, SMEM_DYN);

    prep_kernel<<<CVT_BLOCKS + DQ_BLOCKS, 256>>>(x, qweight, qzeros, scales);
    gemm_hmma_kernel<<<dim3(M_DIM / BM, N_DIM / BN), 256, SMEM_DYN>>>(out);
}

// round 10
// speedup vs baseline: 1.4294x; 1.4294x over previous
#include <cuda_runtime.h>
#include <cuda_fp16.h>
#include <cstdint>

// ---------------------------------------------------------------------------
// Problem dims (fixed)
// ---------------------------------------------------------------------------
#define M_DIM 8192
#define K_DIM 4096
#define N_DIM 11008
#define NPACK 1376   // N/8

// GEMM tiling: CTA 128x128, warp tile 64x32 (2Mx4N), BK=32, 5 stages, 2 CTA/SM
// (byte-exact R7 configuration — best measured GEMM)
#define BM 128
#define BN 128
#define BK 32
#define STAGES 5
#define PITCH_B 80                        // bytes per smem row -> conflict-free ldmatrix
#define A_STAGE_B (BM * PITCH_B)          // 10240 B
#define B_STAGE_B (BN * PITCH_B)          // 10240 B
#define STAGE_B   (A_STAGE_B + B_STAGE_B) // 20480 B
#define SMEM_DYN  (STAGES * STAGE_B)      // 102400 B -> 2 CTAs/SM

// Prep-kernel grid split
#define CVT_BLOCKS  16384                 // M*K/(256*8)
#define DQ_BX 43
#define DQ_BY 256
#define DQ_BLOCKS (DQ_BX * DQ_BY)         // 11008

// Scratch (device globals; no runtime allocation)
__device__ __half A_h[(size_t)M_DIM * K_DIM];   // 67 MB
__device__ __half W_h[(size_t)N_DIM * K_DIM];   // 90 MB, [N][K] (col-major B)

// ---------------------------------------------------------------------------
// PTX helpers (base sm_103 ISA only)
// ---------------------------------------------------------------------------
__device__ __forceinline__ uint32_t smem_u32(const void* p) {
    uint32_t a;
    asm("{ .reg .u64 t; cvta.to.shared.u64 t, %1; cvt.u32.u64 %0, t; }"
        : "=r"(a) : "l"(p));
    return a;
}
__device__ __forceinline__ void cp_async16(uint32_t dst, const void* src) {
    asm volatile("cp.async.cg.shared.global [%0], [%1], 16;"
                 :: "r"(dst), "l"(src) : "memory");
}
__device__ __forceinline__ void cp_commit() {
    asm volatile("cp.async.commit_group;" ::: "memory");
}
template <int N>
__device__ __forceinline__ void cp_wait() {
    asm volatile("cp.async.wait_group %0;" :: "n"(N) : "memory");
}
__device__ __forceinline__ void ldmx4(uint32_t* r, uint32_t addr) {
    asm volatile("ldmatrix.sync.aligned.m8n8.x4.shared.b16 {%0,%1,%2,%3}, [%4];"
                 : "=r"(r[0]), "=r"(r[1]), "=r"(r[2]), "=r"(r[3]) : "r"(addr));
}
__device__ __forceinline__ void mma_f16(float* d, const uint32_t* a, const uint32_t* b) {
    asm volatile(
        "mma.sync.aligned.m16n8k16.row.col.f32.f16.f16.f32 "
        "{%0,%1,%2,%3}, {%4,%5,%6,%7}, {%8,%9}, {%0,%1,%2,%3};"
        : "+f"(d[0]), "+f"(d[1]), "+f"(d[2]), "+f"(d[3])
        : "r"(a[0]), "r"(a[1]), "r"(a[2]), "r"(a[3]), "r"(b[0]), "r"(b[1]));
}

// ---------------------------------------------------------------------------
// Prep kernel: blocks [0, CVT_BLOCKS) convert x -> fp16;
//              blocks [CVT_BLOCKS, +DQ_BLOCKS) GPTQ-dequant -> W_h[n][k]
// ---------------------------------------------------------------------------
__global__ void prep_kernel(const float* __restrict__ x,
                            const int* __restrict__ qweight,
                            const int* __restrict__ qzeros,
                            const float* __restrict__ scales) {
    if (blockIdx.x < CVT_BLOCKS) {
        size_t i = ((size_t)blockIdx.x * 256 + threadIdx.x) * 8;
        float4 v0 = *(const float4*)(x + i);
        float4 v1 = *(const float4*)(x + i + 4);
        __half2 h[4];
        h[0] = __floats2half2_rn(v0.x, v0.y);
        h[1] = __floats2half2_rn(v0.z, v0.w);
        h[2] = __floats2half2_rn(v1.x, v1.y);
        h[3] = __floats2half2_rn(v1.z, v1.w);
        *(uint4*)(A_h + i) = *(uint4*)h;
    } else {
        int b   = blockIdx.x - CVT_BLOCKS;
        int n   = (b % DQ_BX) * 256 + threadIdx.x;
        int kp0 = (b / DQ_BX) * 2;
        int g   = kp0 >> 4;

        unsigned zpack = (unsigned)qzeros[g * NPACK + (n >> 3)];
        int zq = (int)((zpack >> ((n & 7) * 4)) & 0xFu) + 1;
        float s = scales[g * N_DIM + n];

        __half2 out[8];
#pragma unroll
        for (int p = 0; p < 2; ++p) {
            unsigned packed = (unsigned)qweight[(kp0 + p) * N_DIM + n];
#pragma unroll
            for (int j = 0; j < 4; ++j) {
                int q0 = (int)((packed >> (8 * j)) & 0xFu);
                int q1 = (int)((packed >> (8 * j + 4)) & 0xFu);
                out[p * 4 + j] = __floats2half2_rn(s * (float)(q0 - zq),
                                                   s * (float)(q1 - zq));
            }
        }
        __half* dst = W_h + (size_t)n * K_DIM + (size_t)kp0 * 8;
        *(uint4*)(dst)     = *(uint4*)(out);
        *(uint4*)(dst + 8) = *(uint4*)(out + 4);
    }
}

// ---------------------------------------------------------------------------
// GEMM: C = A_h * W_h^T via mma.sync m16n8k16 fp16->fp32
// CTA 128x128, 8 warps (2Mx4N, warp 64x32), BK=32, 5-stage cp.async pipeline,
// 2 CTAs/SM (16 warps). Byte-exact R7 inner loop (best measured).
// ---------------------------------------------------------------------------
__global__ void __launch_bounds__(256, 2)
gemm_hmma_kernel(float* __restrict__ C) {
    extern __shared__ char dynsmem[];
    const uint32_t sbase = smem_u32(dynsmem);

    const int tid  = threadIdx.x;
    const int wid  = tid >> 5;
    const int lane = tid & 31;
    const int m0 = blockIdx.x * BM;
    const int n0 = blockIdx.y * BN;
    const int wm = (wid & 1) * 64;   // warp M offset
    const int wn = (wid >> 1) * 32;  // warp N offset

    // ---- cp.async source/dest mapping: thread -> (row, 32B column) ----
    const int ld_row = tid >> 1;           // 0..127
    const int ld_kc  = (tid & 1) * 16;     // halves (32 B)
    const __half* gA = A_h + (size_t)(m0 + ld_row) * K_DIM + ld_kc;
    const __half* gB = W_h + (size_t)(n0 + ld_row) * K_DIM + ld_kc;
    const uint32_t sA_row = sbase + ld_row * PITCH_B + ld_kc * 2;
    const uint32_t sB_row = sA_row + A_STAGE_B;

    // ---- ldmatrix lane offsets (bytes within a stage) ----
    const uint32_t a_lane = (uint32_t)(wm + (lane & 15)) * PITCH_B
                          + ((lane >> 4) ? 16u : 0u);
    const uint32_t b_lane = A_STAGE_B
                          + (uint32_t)(wn + ((lane >> 4) & 1) * 8 + (lane & 7)) * PITCH_B
                          + (((lane >> 3) & 1) ? 16u : 0u);

    float acc[4][4][4];
#pragma unroll
    for (int i = 0; i < 4; ++i)
#pragma unroll
        for (int t = 0; t < 4; ++t)
#pragma unroll
            for (int r = 0; r < 4; ++r) acc[i][t][r] = 0.f;

    const int NIT = K_DIM / BK;   // 128

    // ---- prologue: stages 0..3 ----
#pragma unroll
    for (int s = 0; s < STAGES - 1; ++s) {
        uint32_t so = (uint32_t)s * STAGE_B;
        const __half* a = gA + s * BK;
        const __half* b = gB + s * BK;
        cp_async16(sA_row + so,      a);
        cp_async16(sA_row + so + 16, a + 8);
        cp_async16(sB_row + so,      b);
        cp_async16(sB_row + so + 16, b + 8);
        cp_commit();
    }

    int st = 0;
    for (int it = 0; it < NIT; ++it) {
        cp_wait<STAGES - 2>();
        __syncthreads();

        // issue stage it+STAGES-1 (or empty group to keep wait-count math valid)
        int kt = it + STAGES - 1;
        if (kt < NIT) {
            int s2 = kt % STAGES;
            uint32_t so = (uint32_t)s2 * STAGE_B;
            const __half* a = gA + kt * BK;
            const __half* b = gB + kt * BK;
            cp_async16(sA_row + so,      a);
            cp_async16(sA_row + so + 16, a + 8);
            cp_async16(sB_row + so,      b);
            cp_async16(sB_row + so + 16, b + 8);
        }
        cp_commit();

        const uint32_t stage = sbase + (uint32_t)st * STAGE_B;
#pragma unroll
        for (int ks = 0; ks < 2; ++ks) {
            uint32_t afr[4][4], bfr[4][2];
#pragma unroll
            for (int i = 0; i < 4; ++i)
                ldmx4(afr[i], stage + a_lane + (uint32_t)i * 16 * PITCH_B + ks * 32);
#pragma unroll
            for (int j = 0; j < 2; ++j) {
                uint32_t r[4];
                ldmx4(r, stage + b_lane + (uint32_t)j * 16 * PITCH_B + ks * 32);
                bfr[2 * j][0] = r[0]; bfr[2 * j][1] = r[1];
                bfr[2 * j + 1][0] = r[2]; bfr[2 * j + 1][1] = r[3];
            }
#pragma unroll
            for (int i = 0; i < 4; ++i)
#pragma unroll
                for (int t = 0; t < 4; ++t)
                    mma_f16(acc[i][t], afr[i], bfr[t]);
        }
        if (++st == STAGES) st = 0;
    }

    // ---- epilogue: direct fp32 stores ----
    const int er = lane >> 2;
    const int ec = (lane & 3) * 2;
#pragma unroll
    for (int i = 0; i < 4; ++i) {
        size_t row0 = (size_t)(m0 + wm + i * 16 + er) * N_DIM;
        size_t row1 = row0 + 8 * N_DIM;
#pragma unroll
        for (int t = 0; t < 4; ++t) {
            int col = n0 + wn + t * 8 + ec;
            *(float2*)(C + row0 + col) = make_float2(acc[i][t][0], acc[i][t][1]);
            *(float2*)(C + row1 + col) = make_float2(acc[i][t][2], acc[i][t][3]);
        }
    }
}

// ---------------------------------------------------------------------------
// Launch
// ---------------------------------------------------------------------------
extern "C" void kernel_launch(void* const* d_in, const int* in_sizes, int n_in,
                              void* d_out, int out_size) {
    const float* x       = (const float*)d_in[0];
    const int*   qweight = (const int*)d_in[1];
    const int*   qzeros  = (const int*)d_in[2];
    const float* scales  = (const float*)d_in[3];
    float* out = (float*)d_out;

    cudaFuncSetAttribute(gemm_hmma_kernel,
                         cudaFuncAttributeMaxDynamicSharedMemorySize, SMEM_DYN);

    prep_kernel<<<CVT_BLOCKS + DQ_BLOCKS, 256>>>(x, qweight, qzeros, scales);
    gemm_hmma_kernel<<<dim3(M_DIM / BM, N_DIM / BN), 256, SMEM_DYN>>>(out);
}

// round 11
// speedup vs baseline: 1.6235x; 1.1357x over previous
#include <cuda_runtime.h>
#include <cuda_fp16.h>
#include <cstdint>

// ---------------------------------------------------------------------------
// Problem dims (fixed)
// ---------------------------------------------------------------------------
#define M_DIM 8192
#define K_DIM 4096
#define N_DIM 11008
#define NPACK 1376   // N/8

// GEMM tiling: CTA 128x128, 512 threads, warp tile 32x32 (4Mx4N), BK=32,
// 5 stages, 2 CTA/SM -> 32 warps/SM
#define BM 128
#define BN 128
#define BK 32
#define STAGES 5
#define PITCH_B 80                        // bytes per smem row -> conflict-free ldmatrix
#define A_STAGE_B (BM * PITCH_B)          // 10240 B
#define B_STAGE_B (BN * PITCH_B)          // 10240 B
#define STAGE_B   (A_STAGE_B + B_STAGE_B) // 20480 B
#define SMEM_DYN  (STAGES * STAGE_B)      // 102400 B -> 2 CTAs/SM

// Prep-kernel grid split
#define CVT_BLOCKS  16384                 // M*K/(256*8)
#define DQ_BX 43
#define DQ_BY 256
#define DQ_BLOCKS (DQ_BX * DQ_BY)         // 11008

// Scratch (device globals; no runtime allocation)
__device__ __half A_h[(size_t)M_DIM * K_DIM];   // 67 MB
__device__ __half W_h[(size_t)N_DIM * K_DIM];   // 90 MB, [N][K] (col-major B)

// ---------------------------------------------------------------------------
// PTX helpers (base sm_103 ISA only)
// ---------------------------------------------------------------------------
__device__ __forceinline__ uint32_t smem_u32(const void* p) {
    uint32_t a;
    asm("{ .reg .u64 t; cvta.to.shared.u64 t, %1; cvt.u32.u64 %0, t; }"
        : "=r"(a) : "l"(p));
    return a;
}
__device__ __forceinline__ void cp_async16(uint32_t dst, const void* src) {
    asm volatile("cp.async.cg.shared.global [%0], [%1], 16;"
                 :: "r"(dst), "l"(src) : "memory");
}
__device__ __forceinline__ void cp_commit() {
    asm volatile("cp.async.commit_group;" ::: "memory");
}
template <int N>
__device__ __forceinline__ void cp_wait() {
    asm volatile("cp.async.wait_group %0;" :: "n"(N) : "memory");
}
__device__ __forceinline__ void ldmx4(uint32_t* r, uint32_t addr) {
    asm volatile("ldmatrix.sync.aligned.m8n8.x4.shared.b16 {%0,%1,%2,%3}, [%4];"
                 : "=r"(r[0]), "=r"(r[1]), "=r"(r[2]), "=r"(r[3]) : "r"(addr));
}
__device__ __forceinline__ void mma_f16(float* d, const uint32_t* a, const uint32_t* b) {
    asm volatile(
        "mma.sync.aligned.m16n8k16.row.col.f32.f16.f16.f32 "
        "{%0,%1,%2,%3}, {%4,%5,%6,%7}, {%8,%9}, {%0,%1,%2,%3};"
        : "+f"(d[0]), "+f"(d[1]), "+f"(d[2]), "+f"(d[3])
        : "r"(a[0]), "r"(a[1]), "r"(a[2]), "r"(a[3]), "r"(b[0]), "r"(b[1]));
}

// ---------------------------------------------------------------------------
// Prep kernel: blocks [0, CVT_BLOCKS) convert x -> fp16;
//              blocks [CVT_BLOCKS, +DQ_BLOCKS) GPTQ-dequant -> W_h[n][k]
// ---------------------------------------------------------------------------
__global__ void prep_kernel(const float* __restrict__ x,
                            const int* __restrict__ qweight,
                            const int* __restrict__ qzeros,
                            const float* __restrict__ scales) {
    if (blockIdx.x < CVT_BLOCKS) {
        size_t i = ((size_t)blockIdx.x * 256 + threadIdx.x) * 8;
        float4 v0 = *(const float4*)(x + i);
        float4 v1 = *(const float4*)(x + i + 4);
        __half2 h[4];
        h[0] = __floats2half2_rn(v0.x, v0.y);
        h[1] = __floats2half2_rn(v0.z, v0.w);
        h[2] = __floats2half2_rn(v1.x, v1.y);
        h[3] = __floats2half2_rn(v1.z, v1.w);
        *(uint4*)(A_h + i) = *(uint4*)h;
    } else {
        int b   = blockIdx.x - CVT_BLOCKS;
        int n   = (b % DQ_BX) * 256 + threadIdx.x;
        int kp0 = (b / DQ_BX) * 2;
        int g   = kp0 >> 4;

        unsigned zpack = (unsigned)qzeros[g * NPACK + (n >> 3)];
        int zq = (int)((zpack >> ((n & 7) * 4)) & 0xFu) + 1;
        float s = scales[g * N_DIM + n];

        __half2 out[8];
#pragma unroll
        for (int p = 0; p < 2; ++p) {
            unsigned packed = (unsigned)qweight[(kp0 + p) * N_DIM + n];
#pragma unroll
            for (int j = 0; j < 4; ++j) {
                int q0 = (int)((packed >> (8 * j)) & 0xFu);
                int q1 = (int)((packed >> (8 * j + 4)) & 0xFu);
                out[p * 4 + j] = __floats2half2_rn(s * (float)(q0 - zq),
                                                   s * (float)(q1 - zq));
            }
        }
        __half* dst = W_h + (size_t)n * K_DIM + (size_t)kp0 * 8;
        *(uint4*)(dst)     = *(uint4*)(out);
        *(uint4*)(dst + 8) = *(uint4*)(out + 4);
    }
}

// ---------------------------------------------------------------------------
// GEMM: C = A_h * W_h^T via mma.sync m16n8k16 fp16->fp32
// CTA 128x128, 512 threads: 16 warps in 4Mx4N grid, warp tile 32x32.
// BK=32, 5-stage cp.async pipeline, 2 CTAs/SM -> 32 warps/SM for latency
// hiding (the profiled limiter: issue 16.4%, no pipe saturated).
// ---------------------------------------------------------------------------
__global__ void __launch_bounds__(512, 2)
gemm_hmma_kernel(float* __restrict__ C) {
    extern __shared__ char dynsmem[];
    const uint32_t sbase = smem_u32(dynsmem);

    const int tid  = threadIdx.x;
    const int wid  = tid >> 5;
    const int lane = tid & 31;
    const int m0 = blockIdx.x * BM;
    const int n0 = blockIdx.y * BN;
    const int wm = (wid & 3) * 32;   // warp M offset
    const int wn = (wid >> 2) * 32;  // warp N offset

    // ---- cp.async mapping: 512 threads, 1 x 16B chunk per matrix each ----
    const int ld_row = tid >> 2;           // 0..127
    const int ld_c   = (tid & 3) * 8;      // halves (16 B chunk)
    const __half* gA = A_h + (size_t)(m0 + ld_row) * K_DIM + ld_c;
    const __half* gB = W_h + (size_t)(n0 + ld_row) * K_DIM + ld_c;
    const uint32_t sA_row = sbase + ld_row * PITCH_B + ld_c * 2;
    const uint32_t sB_row = sA_row + A_STAGE_B;

    // ---- ldmatrix lane offsets (bytes within a stage) ----
    const uint32_t a_lane = (uint32_t)(wm + (lane & 15)) * PITCH_B
                          + ((lane >> 4) ? 16u : 0u);
    const uint32_t b_lane = A_STAGE_B
                          + (uint32_t)(wn + ((lane >> 4) & 1) * 8 + (lane & 7)) * PITCH_B
                          + (((lane >> 3) & 1) ? 16u : 0u);

    float acc[2][4][4];
#pragma unroll
    for (int i = 0; i < 2; ++i)
#pragma unroll
        for (int t = 0; t < 4; ++t)
#pragma unroll
            for (int r = 0; r < 4; ++r) acc[i][t][r] = 0.f;

    const int NIT = K_DIM / BK;   // 128

    // ---- prologue: fill stages 0..3 ----
#pragma unroll
    for (int s = 0; s < STAGES - 1; ++s) {
        uint32_t so = (uint32_t)s * STAGE_B;
        cp_async16(sA_row + so, gA + s * BK);
        cp_async16(sB_row + so, gB + s * BK);
        cp_commit();
    }

    int st = 0;
    for (int it = 0; it < NIT; ++it) {
        cp_wait<STAGES - 2>();
        __syncthreads();

        int kt = it + STAGES - 1;
        if (kt < NIT) {
            uint32_t so = (uint32_t)(kt % STAGES) * STAGE_B;
            cp_async16(sA_row + so, gA + kt * BK);
            cp_async16(sB_row + so, gB + kt * BK);
        }
        cp_commit();

        const uint32_t stage = sbase + (uint32_t)st * STAGE_B;
#pragma unroll
        for (int ks = 0; ks < 2; ++ks) {
            uint32_t afr[2][4], bfr[4][2];
#pragma unroll
            for (int i = 0; i < 2; ++i)
                ldmx4(afr[i], stage + a_lane + (uint32_t)i * 16 * PITCH_B + ks * 32);
#pragma unroll
            for (int j = 0; j < 2; ++j) {
                uint32_t r[4];
                ldmx4(r, stage + b_lane + (uint32_t)j * 16 * PITCH_B + ks * 32);
                bfr[2 * j][0] = r[0]; bfr[2 * j][1] = r[1];
                bfr[2 * j + 1][0] = r[2]; bfr[2 * j + 1][1] = r[3];
            }
#pragma unroll
            for (int i = 0; i < 2; ++i)
#pragma unroll
                for (int t = 0; t < 4; ++t)
                    mma_f16(acc[i][t], afr[i], bfr[t]);
        }
        if (++st == STAGES) st = 0;
    }

    // ---- epilogue: direct fp32 stores ----
    const int er = lane >> 2;
    const int ec = (lane & 3) * 2;
#pragma unroll
    for (int i = 0; i < 2; ++i) {
        size_t row0 = (size_t)(m0 + wm + i * 16 + er) * N_DIM;
        size_t row1 = row0 + 8 * N_DIM;
#pragma unroll
        for (int t = 0; t < 4; ++t) {
            int col = n0 + wn + t * 8 + ec;
            *(float2*)(C + row0 + col) = make_float2(acc[i][t][0], acc[i][t][1]);
            *(float2*)(C + row1 + col) = make_float2(acc[i][t][2], acc[i][t][3]);
        }
    }
}

// ---------------------------------------------------------------------------
// Launch
// ---------------------------------------------------------------------------
extern "C" void kernel_launch(void* const* d_in, const int* in_sizes, int n_in,
                              void* d_out, int out_size) {
    const float* x       = (const float*)d_in[0];
    const int*   qweight = (const int*)d_in[1];
    const int*   qzeros  = (const int*)d_in[2];
    const float* scales  = (const float*)d_in[3];
    float* out = (float*)d_out;

    cudaFuncSetAttribute(gemm_hmma_kernel,
                         cudaFuncAttributeMaxDynamicSharedMemorySize, SMEM_DYN);

    prep_kernel<<<CVT_BLOCKS + DQ_BLOCKS, 256>>>(x, qweight, qzeros, scales);
    gemm_hmma_kernel<<<dim3(M_DIM / BM, N_DIM / BN), 512, SMEM_DYN>>>(out);
}